// round 16
// baseline (speedup 1.0000x reference)
#include <cuda_runtime.h>
#include <cstdint>

#define BATCH   8192
#define HB      4096      // half batch (pipeline slice)
#define FEAT    128
#define DEG     32
#define KSEL    16
#define EMB     128

// ---------------- scratch (static device arrays; no allocation) ----------------
__device__ float g_xbuf[BATCH * FEAT];          // self feats   [B,128]
__device__ float g_agg [3 * BATCH * FEAT];      // agg feats -> overwritten by E_r

// ---------------- f32x2 packed-FMA helpers ----------------
__device__ __forceinline__ unsigned long long pk2(float x, float y) {
    unsigned int xu = __float_as_uint(x), yu = __float_as_uint(y);
    unsigned long long r;
    asm("mov.b64 %0, {%1, %2};" : "=l"(r) : "r"(xu), "r"(yu));
    return r;
}
__device__ __forceinline__ void upk2(unsigned long long v, float& x, float& y) {
    unsigned int lo, hi;
    asm("mov.b64 {%0, %1}, %2;" : "=r"(lo), "=r"(hi) : "l"(v));
    x = __uint_as_float(lo);
    y = __uint_as_float(hi);
}
__device__ __forceinline__ void ffma2(unsigned long long& d,
                                      unsigned long long a,
                                      unsigned long long b) {
    asm("fma.rn.f32x2 %0, %1, %2, %0;" : "+l"(d) : "l"(a), "l"(b));
}

// ---------------- Kernel B: gather + score + top-K + mean (DRAM-bound) ----------------
__global__ __launch_bounds__(128) void agg_kernel(const float* __restrict__ feat,
                                                  const float* __restrict__ Wclf,
                                                  const float* __restrict__ bclf,
                                                  const int*   __restrict__ nodes,
                                                  const int*   __restrict__ n1,
                                                  const int*   __restrict__ n2,
                                                  const int*   __restrict__ n3,
                                                  int b0) {
    const int b   = blockIdx.x + b0;
    const int rel = blockIdx.y;
    const int* nb = (rel == 0) ? n1 : (rel == 1) ? n2 : n3;

    __shared__ __align__(16) float spart[4][132];
    __shared__ float    sscore[DEG];
    __shared__ float    scs0;
    __shared__ unsigned smask;

    const int t = threadIdx.x;
    const int w = t >> 5, l = t & 31;

    float w00 = __ldg(Wclf + 8 * l);
    float w01 = __ldg(Wclf + 8 * l + 2);
    float w02 = __ldg(Wclf + 8 * l + 4);
    float w03 = __ldg(Wclf + 8 * l + 6);
    float bias0 = __ldg(bclf);

    int nidx[8];
    #pragma unroll
    for (int r = 0; r < 8; r++)
        nidx[r] = __ldg(nb + b * DEG + w + 4 * r);
    float4 cf;
    if (w == 0) {
        long cb = (long)__ldg(nodes + b) * FEAT;
        cf = __ldg((const float4*)(feat + cb) + l);
    }
    float4 f[8];
    #pragma unroll
    for (int r = 0; r < 8; r++)
        f[r] = __ldg((const float4*)(feat + (long)nidx[r] * FEAT) + l);

    float p[8];
    #pragma unroll
    for (int r = 0; r < 8; r++)
        p[r] = f[r].x * w00 + f[r].y * w01 + f[r].z * w02 + f[r].w * w03;
    #pragma unroll
    for (int o = 16; o; o >>= 1) {
        #pragma unroll
        for (int r = 0; r < 8; r++)
            p[r] += __shfl_xor_sync(0xffffffffu, p[r], o);
    }
    if (l == 0) {
        #pragma unroll
        for (int r = 0; r < 8; r++)
            sscore[w + 4 * r] = p[r] + bias0;
    }
    if (w == 0) {
        float pc = cf.x * w00 + cf.y * w01 + cf.z * w02 + cf.w * w03;
        #pragma unroll
        for (int o = 16; o; o >>= 1) pc += __shfl_xor_sync(0xffffffffu, pc, o);
        if (l == 0) scs0 = pc + bias0;
    }
    __syncthreads();

    if (t < DEG) {
        float cs0 = scs0;
        float di = fabsf(sscore[t] - cs0);
        int rank = 0;
        #pragma unroll
        for (int j = 0; j < DEG; j++) {
            float dj = fabsf(sscore[j] - cs0);
            rank += (dj < di) || (dj == di && j < t);
        }
        unsigned m = __ballot_sync(0xffffffffu, rank < KSEL);
        if (t == 0) smask = m;
    }
    __syncthreads();

    const unsigned m = smask;
    float4 acc = make_float4(0.f, 0.f, 0.f, 0.f);
    #pragma unroll
    for (int r = 0; r < 8; r++) {
        if (m & (1u << (w + 4 * r))) {
            acc.x += f[r].x; acc.y += f[r].y; acc.z += f[r].z; acc.w += f[r].w;
        }
    }
    *(float4*)&spart[w][4 * l] = acc;
    __syncthreads();

    float s = spart[0][t] + spart[1][t] + spart[2][t] + spart[3][t];
    g_agg[((long)rel * BATCH + b) * FEAT + t] = s * (1.0f / KSEL);
}

// ---------------- Kernel A: self gather + center scores ----------------
__global__ __launch_bounds__(256) void self_score_kernel(const float* __restrict__ feat,
                                                         const float* __restrict__ Wclf,
                                                         const float* __restrict__ bclf,
                                                         const int*   __restrict__ nodes,
                                                         float* __restrict__ out_cs,
                                                         int b0) {
    int wg = threadIdx.x >> 5, l = threadIdx.x & 31;
    int b = blockIdx.x * 8 + wg + b0;
    long base = (long)__ldg(nodes + b) * FEAT;
    float4 f = __ldg((const float4*)(feat + base) + l);
    *(float4*)(g_xbuf + b * FEAT + 4 * l) = f;
    float4 wAB0 = __ldg((const float4*)Wclf + 2 * l);
    float4 wAB1 = __ldg((const float4*)Wclf + 2 * l + 1);
    float p0 = f.x * wAB0.x + f.y * wAB0.z + f.z * wAB1.x + f.w * wAB1.z;
    float p1 = f.x * wAB0.y + f.y * wAB0.w + f.z * wAB1.y + f.w * wAB1.w;
    #pragma unroll
    for (int o = 16; o; o >>= 1) {
        p0 += __shfl_xor_sync(0xffffffffu, p0, o);
        p1 += __shfl_xor_sync(0xffffffffu, p1, o);
    }
    if (l == 0) {
        out_cs[b * 2]     = p0 + __ldg(bclf);
        out_cs[b * 2 + 1] = p1 + __ldg(bclf + 1);
    }
}

// ================= GEMM stage: 8x8 micro-tile + warpgroup split-K =================

#define WCHUNK (16 * 128)   // floats per W chunk
#define ACHUNK (64 * 16)    // floats per A chunk

__device__ __forceinline__ void mma8(const float* __restrict__ A,
                                     const float* __restrict__ sW,
                                     int c0, unsigned long long acc[8][4]) {
    #pragma unroll
    for (int q = 0; q < 4; q++) {
        float4 av[8];
        #pragma unroll
        for (int i = 0; i < 8; i++)
            av[i] = *(const float4*)&A[i * 16 + 4 * q];
        #pragma unroll
        for (int k = 0; k < 4; k++) {
            int k2 = 4 * q + k;
            ulonglong2 b01 = *(const ulonglong2*)&sW[k2 * 128 + c0];
            ulonglong2 b23 = *(const ulonglong2*)&sW[k2 * 128 + c0 + 4];
            #pragma unroll
            for (int i = 0; i < 8; i++) {
                float a = (k == 0) ? av[i].x : (k == 1) ? av[i].y
                        : (k == 2) ? av[i].z : av[i].w;
                unsigned long long ap = pk2(a, a);
                ffma2(acc[i][0], ap, b01.x);
                ffma2(acc[i][1], ap, b01.y);
                ffma2(acc[i][2], ap, b23.x);
                ffma2(acc[i][3], ap, b23.y);
            }
        }
    }
}

__device__ __forceinline__ void ldW(const float* __restrict__ W, int kk, int wt,
                                    float4 w[4]) {
    #pragma unroll
    for (int i = 0; i < 4; i++)
        w[i] = __ldg((const float4*)(W + kk * 128) + wt + i * 128);
}
__device__ __forceinline__ void stW(float* __restrict__ sW, int wt, const float4 w[4]) {
    #pragma unroll
    for (int i = 0; i < 4; i++)
        *(float4*)&sW[(wt + i * 128) * 4] = w[i];
}
__device__ __forceinline__ void ldA(const float* __restrict__ src, int bm, int kk,
                                    int wt, float4 a[2]) {
    #pragma unroll
    for (int i = 0; i < 2; i++) {
        int e = wt + i * 128;
        int row = e >> 2, c4 = e & 3;
        a[i] = __ldg((const float4*)(src + (long)(bm + row) * FEAT + kk) + c4);
    }
}
__device__ __forceinline__ void stA(float* __restrict__ sA, int wt, const float4 a[2]) {
    #pragma unroll
    for (int i = 0; i < 2; i++) {
        int e = wt + i * 128;
        int row = e >> 2, c4 = e & 3;
        *(float4*)&sA[row * 16 + c4 * 4] = a[i];
    }
}

template <int NCHUNK, int NSRC>
__device__ __forceinline__ void gemm_splitk(const float* __restrict__ W,
                                            const float* const srcs[NSRC],
                                            int bm, float* smem,
                                            unsigned long long acc[8][4],
                                            int& grp, int& r0, int& c0) {
    const int tid = threadIdx.x;
    grp = tid >> 7;
    const int wt = tid & 127;
    const int colg = wt & 15, rowg = wt >> 4;
    r0 = rowg * 8; c0 = colg * 8;

    float* sWg = smem + grp * 2 * WCHUNK;
    float* sAg = smem + 4 * WCHUNK + grp * 2 * ACHUNK;

    #pragma unroll
    for (int i = 0; i < 8; i++)
        #pragma unroll
        for (int j = 0; j < 4; j++) acc[i][j] = 0ull;

    const int half = NCHUNK / 2;
    const int ck0 = grp * half;
    const int kk0 = ck0 * 16;
    float4 w[4], a[2];
    ldW(W, kk0, wt, w);
    ldA(srcs[kk0 >> 7], bm, kk0 & 127, wt, a);   // src boundary every 128 K
    #pragma unroll 1
    for (int s = 0; s < half; s++) {
        int ck = ck0 + s;
        float* bw = sWg + (s & 1) * WCHUNK;
        float* ba = sAg + (s & 1) * ACHUNK;
        stW(bw, wt, w);
        stA(ba, wt, a);
        __syncthreads();
        if (s < half - 1) {
            int kn = (ck + 1) * 16;
            ldW(W, kn, wt, w);
            ldA(srcs[kn >> 7], bm, kn & 127, wt, a);
        }
        mma8(ba + r0 * 16, bw, c0, acc);
        __syncthreads();
    }

    // cross-group reduction: group 1 dumps, group 0 accumulates.
    float* red = smem;   // 32 KB region, lane stride 2 floats (conflict-free)
    if (grp == 1) {
        #pragma unroll
        for (int i = 0; i < 8; i++)
            #pragma unroll
            for (int j = 0; j < 4; j++)
                *(unsigned long long*)&red[(i * 4 + j) * 256 + wt * 2] = acc[i][j];
    }
    __syncthreads();
    if (grp == 0) {
        #pragma unroll
        for (int i = 0; i < 8; i++)
            #pragma unroll
            for (int j = 0; j < 4; j++) {
                float x0, y0, x1, y1;
                upk2(acc[i][j], x0, y0);
                upk2(*(const unsigned long long*)&red[(i * 4 + j) * 256 + wt * 2], x1, y1);
                acc[i][j] = pk2(x0 + x1, y0 + y1);
            }
    }
}

// ---------------- Kernel C1: intra GEMMs ----------------
__global__ __launch_bounds__(256, 1) void intra_kernel(const float* __restrict__ Wi1,
                                                       const float* __restrict__ Wi2,
                                                       const float* __restrict__ Wi3,
                                                       int b0) {
    extern __shared__ __align__(16) float smem[];
    const int bm  = blockIdx.x * 64 + b0;
    const int rel = blockIdx.y;
    const float* W = (rel == 0) ? Wi1 : (rel == 1) ? Wi2 : Wi3;
    const float* srcs[2] = {g_xbuf, g_agg + (long)rel * BATCH * FEAT};

    unsigned long long acc[8][4];
    int grp, r0, c0;
    gemm_splitk<16, 2>(W, srcs, bm, smem, acc, grp, r0, c0);

    if (grp == 0) {
        #pragma unroll
        for (int i = 0; i < 8; i++) {
            float v[8];
            #pragma unroll
            for (int j = 0; j < 4; j++) upk2(acc[i][j], v[2 * j], v[2 * j + 1]);
            float4 o0 = make_float4(fmaxf(v[0], 0.f), fmaxf(v[1], 0.f),
                                    fmaxf(v[2], 0.f), fmaxf(v[3], 0.f));
            float4 o1 = make_float4(fmaxf(v[4], 0.f), fmaxf(v[5], 0.f),
                                    fmaxf(v[6], 0.f), fmaxf(v[7], 0.f));
            float* dst = g_agg + ((long)rel * BATCH + bm + r0 + i) * FEAT + c0;
            *(float4*)dst       = o0;
            *(float4*)(dst + 4) = o1;
        }
    }
}

// ---------------- Kernel C2: comb GEMM ----------------
__global__ __launch_bounds__(256, 1) void comb_kernel(const float* __restrict__ Wc,
                                                      float* __restrict__ out,
                                                      int b0) {
    extern __shared__ __align__(16) float smem[];
    const int bm = blockIdx.x * 64 + b0;
    const float* srcs[4] = {g_xbuf,
                            g_agg,
                            g_agg + (long)BATCH * FEAT,
                            g_agg + 2L * BATCH * FEAT};

    unsigned long long acc[8][4];
    int grp, r0, c0;
    gemm_splitk<32, 4>(Wc, srcs, bm, smem, acc, grp, r0, c0);

    if (grp == 0) {
        float v[8][8];
        #pragma unroll
        for (int i = 0; i < 8; i++)
            #pragma unroll
            for (int j = 0; j < 4; j++) upk2(acc[i][j], v[i][2 * j], v[i][2 * j + 1]);
        #pragma unroll
        for (int j = 0; j < 8; j++) {
            float4 o0 = make_float4(fmaxf(v[0][j], 0.f), fmaxf(v[1][j], 0.f),
                                    fmaxf(v[2][j], 0.f), fmaxf(v[3][j], 0.f));
            float4 o1 = make_float4(fmaxf(v[4][j], 0.f), fmaxf(v[5][j], 0.f),
                                    fmaxf(v[6][j], 0.f), fmaxf(v[7][j], 0.f));
            float* dst = out + (long)(c0 + j) * BATCH + bm + r0;
            *(float4*)dst       = o0;
            *(float4*)(dst + 4) = o1;
        }
    }
}

// ---------------- launch: 2-slice pipeline across two streams ----------------
extern "C" void kernel_launch(void* const* d_in, const int* in_sizes, int n_in,
                              void* d_out, int out_size) {
    const float* feat  = (const float*)d_in[0];
    const float* Wclf  = (const float*)d_in[1];
    const float* bclf  = (const float*)d_in[2];
    const float* Wi1   = (const float*)d_in[3];
    const float* Wi2   = (const float*)d_in[4];
    const float* Wi3   = (const float*)d_in[5];
    const float* Wc    = (const float*)d_in[6];
    const int*   nodes = (const int*)d_in[7];
    const int*   n1    = (const int*)d_in[8];
    const int*   n2    = (const int*)d_in[9];
    const int*   n3    = (const int*)d_in[10];

    float* out    = (float*)d_out;
    float* out_cs = out + (long)EMB * BATCH;   // center_scores after combined

    int smemG = (4 * WCHUNK + 4 * ACHUNK) * sizeof(float);  // 48 KB
    cudaFuncSetAttribute(intra_kernel,
                         cudaFuncAttributeMaxDynamicSharedMemorySize, smemG);
    cudaFuncSetAttribute(comb_kernel,
                         cudaFuncAttributeMaxDynamicSharedMemorySize, smemG);

    // host-side objects only (no device memory); kernel_launch runs ~2x
    // (correctness + capture), replays use the captured DAG.
    cudaStream_t s1;
    cudaEvent_t  evFork, evJoin;
    cudaStreamCreateWithFlags(&s1, cudaStreamNonBlocking);
    cudaEventCreateWithFlags(&evFork, cudaEventDisableTiming);
    cudaEventCreateWithFlags(&evJoin, cudaEventDisableTiming);

    dim3 gridBh(HB, 3);
    dim3 gridIh(HB / 64, 3);

    // slice 0 gather on main (legacy) stream
    agg_kernel<<<gridBh, 128>>>(feat, Wclf, bclf, nodes, n1, n2, n3, 0);
    cudaEventRecord(evFork, 0);

    // slice 0 chain on side stream, overlapping slice 1 gather on main
    cudaStreamWaitEvent(s1, evFork, 0);
    self_score_kernel<<<HB / 8, 256, 0, s1>>>(feat, Wclf, bclf, nodes, out_cs, 0);
    intra_kernel<<<gridIh, 256, smemG, s1>>>(Wi1, Wi2, Wi3, 0);
    comb_kernel<<<HB / 64, 256, smemG, s1>>>(Wc, out, 0);
    cudaEventRecord(evJoin, s1);

    // slice 1 on main stream
    agg_kernel<<<gridBh, 128>>>(feat, Wclf, bclf, nodes, n1, n2, n3, HB);
    self_score_kernel<<<HB / 8, 256>>>(feat, Wclf, bclf, nodes, out_cs, HB);
    intra_kernel<<<gridIh, 256, smemG>>>(Wi1, Wi2, Wi3, HB);
    comb_kernel<<<HB / 64, 256, smemG>>>(Wc, out, HB);

    // join side stream back into main before returning
    cudaStreamWaitEvent(0, evJoin, 0);
}